// round 1
// baseline (speedup 1.0000x reference)
#include <cuda_runtime.h>
#include <cstdint>

static constexpr int NB   = 8;     // batch
static constexpr int NN   = 384;   // nodes
static constexpr int NF   = 64;    // features
static constexpr int NT   = 192;   // T (sink shift, also N_SINK)
static constexpr int NS   = 5;     // gumbel samples
static constexpr int NSRC = 383;   // source grid width

// Scratch: factored first-layer projections.
__device__ float g_P [NB * NN * NF];   // P[b][n][f]  = nodes[b,n]@w1[:64] + b1   (sink half)
__device__ float g_Qt[NB * NF * NN];   // Qt[b][f][n] = (nodes[b,n]@w1[64:])^T    (source half)

// ---------------------------------------------------------------------------
// Kernel 1: projection (tiny: 25 MFMA total)
// ---------------------------------------------------------------------------
__global__ void proj_kernel(const float* __restrict__ nodes,
                            const float* __restrict__ w1,
                            const float* __restrict__ b1) {
    int bn = blockIdx.x;           // 0..NB*NN-1
    int j  = threadIdx.x;          // 0..63
    __shared__ float nd[NF];
    nd[j] = nodes[bn * NF + j];
    __syncthreads();
    float accP = b1[j], accQ = 0.f;
#pragma unroll
    for (int f = 0; f < NF; ++f) {
        accP = fmaf(nd[f], w1[f * NF + j], accP);
        accQ = fmaf(nd[f], w1[(NF + f) * NF + j], accQ);
    }
    g_P[bn * NF + j] = accP;
    int b = bn / NN, n = bn % NN;
    g_Qt[(b * NF + j) * NN + n] = accQ;
}

// ---------------------------------------------------------------------------
// Kernel 2: per-edge MLP + per-sample argmax + output write.
// Block = (sink row k, batch b). Thread = one edge (source c), strided.
// ---------------------------------------------------------------------------
__global__ __launch_bounds__(256) void edge_kernel(
    const float* __restrict__ g1,  const float* __restrict__ be1,
    const float* __restrict__ w2,  const float* __restrict__ b2,
    const float* __restrict__ g2,  const float* __restrict__ be2,
    const float* __restrict__ w3,  const float* __restrict__ b3,
    const float* __restrict__ gumbel,
    float* __restrict__ out)
{
    const int k = blockIdx.x;            // sink index 0..191
    const int b = blockIdx.y;            // batch
    const int r = k + NT;                // sink node id 192..383
    const int nsrc = r;                  // valid sources: c in [0, r)
    const int tid = threadIdx.x;

    __shared__ float sW2[NF * NF];       // 16 KB
    __shared__ float sPr[NF], sG1[NF], sBe1[NF], sB2[NF], sGw[NF];
    __shared__ float sLog[NN];
    __shared__ float sSel[NN];
    __shared__ float sGsum, sC;

    for (int i = tid; i < NF * NF; i += 256) sW2[i] = w2[i];
    if (tid < NF) {
        sPr[tid]  = g_P[(b * NN + r) * NF + tid];
        sG1[tid]  = g1[tid];
        sBe1[tid] = be1[tid];
        sB2[tid]  = b2[tid];
        sGw[tid]  = g2[tid] * w3[tid];
    }
    for (int i = tid; i < NN; i += 256) sSel[i] = 0.f;
    if (tid == 0) {
        float gs = 0.f, cc = b3[0];
        for (int o = 0; o < NF; ++o) { gs += g2[o] * w3[o]; cc += be2[o] * w3[o]; }
        sGsum = gs; sC = cc;
    }
    __syncthreads();

    // ---- per-edge MLP ----
    for (int c = tid; c < nsrc; c += 256) {
        const float* qp = g_Qt + b * NF * NN + c;   // Qt[b][j][c], stride NN over j
        float x[NF];
        float s = 0.f, s2 = 0.f;
#pragma unroll
        for (int j = 0; j < NF; ++j) {
            float v = sPr[j] + qp[j * NN];
            v = fmaxf(v, 0.f);
            x[j] = v;
            s += v;
            s2 = fmaf(v, v, s2);
        }
        const float inv = 1.f / NF;
        float mu   = s * inv;
        float rstd = rsqrtf(fmaf(-mu, mu, s2 * inv) + 1e-5f);
#pragma unroll
        for (int j = 0; j < NF; ++j)
            x[j] = fmaf((x[j] - mu) * rstd, sG1[j], sBe1[j]);

        // h2 = relu(x @ w2 + b2); fold LN2 + w3 into running sums.
        float S1 = 0.f, Sq = 0.f, S3 = 0.f;
#pragma unroll 1
        for (int oc = 0; oc < NF; oc += 16) {
            unsigned long long acc[8];
#pragma unroll
            for (int p = 0; p < 8; ++p) {
                float b0 = sB2[oc + 2 * p], b1v = sB2[oc + 2 * p + 1];
                asm("mov.b64 %0, {%1, %2};" : "=l"(acc[p]) : "f"(b0), "f"(b1v));
            }
#pragma unroll
            for (int j = 0; j < NF; ++j) {
                unsigned long long xd;
                asm("mov.b64 %0, {%1, %1};" : "=l"(xd) : "f"(x[j]));
                const float4* wrow = (const float4*)&sW2[j * NF + oc];
#pragma unroll
                for (int q = 0; q < 4; ++q) {
                    float4 w4 = wrow[q];
                    unsigned long long w01, w23;
                    asm("mov.b64 %0, {%1, %2};" : "=l"(w01) : "f"(w4.x), "f"(w4.y));
                    asm("mov.b64 %0, {%1, %2};" : "=l"(w23) : "f"(w4.z), "f"(w4.w));
                    asm("fma.rn.f32x2 %0, %1, %2, %0;" : "+l"(acc[2 * q    ]) : "l"(xd), "l"(w01));
                    asm("fma.rn.f32x2 %0, %1, %2, %0;" : "+l"(acc[2 * q + 1]) : "l"(xd), "l"(w23));
                }
            }
#pragma unroll
            for (int p = 0; p < 8; ++p) {
                float v0, v1;
                asm("mov.b64 {%0, %1}, %2;" : "=f"(v0), "=f"(v1) : "l"(acc[p]));
                v0 = fmaxf(v0, 0.f); v1 = fmaxf(v1, 0.f);
                S1 += v0 + v1;
                Sq = fmaf(v0, v0, Sq); Sq = fmaf(v1, v1, Sq);
                S3 = fmaf(v0, sGw[oc + 2 * p], S3);
                S3 = fmaf(v1, sGw[oc + 2 * p + 1], S3);
            }
        }
        float mu2   = S1 * (1.f / NF);
        float rstd2 = rsqrtf(fmaf(-mu2, mu2, Sq * (1.f / NF)) + 1e-5f);
        sLog[c] = fmaf(rstd2, fmaf(-mu2, sGsum, S3), sC);
    }
    __syncthreads();

    // ---- per-sample argmax over logit + gumbel (argmax(softmax(z)) == argmax(z)) ----
    int wid = tid >> 5, lane = tid & 31;
    if (wid < NS) {
        const float* gu = gumbel + (((size_t)wid * NB + b) * NT + k) * NSRC;
        float best = -__int_as_float(0x7f800000);  // -inf
        int   bi   = 0;
        for (int c = lane; c < nsrc; c += 32) {
            float v = sLog[c] + gu[c];
            if (v > best) { best = v; bi = c; }     // first-index tiebreak within lane
        }
#pragma unroll
        for (int off = 16; off; off >>= 1) {
            float ov = __shfl_down_sync(0xffffffffu, best, off);
            int   oi = __shfl_down_sync(0xffffffffu, bi,   off);
            if (ov > best || (ov == best && oi < bi)) { best = ov; bi = oi; }
        }
        if (lane == 0) sSel[bi] = 1.f;              // union over samples (e>0 binarize)
    }
    __syncthreads();

    // ---- write output: row r (selections, zeros beyond) and row k (all zero).
    // Every (b,row) of the 8x384x384 output is covered exactly once -> no memset needed.
    float* rowR = out + ((size_t)b * NN + r) * NN;
    float* rowK = out + ((size_t)b * NN + k) * NN;
    for (int c = tid; c < NN; c += 256) {
        rowR[c] = sSel[c];
        rowK[c] = 0.f;
    }
}

// ---------------------------------------------------------------------------
extern "C" void kernel_launch(void* const* d_in, const int* in_sizes, int n_in,
                              void* d_out, int out_size) {
    const float* nodes  = (const float*)d_in[0];
    const float* w1     = (const float*)d_in[1];
    const float* b1     = (const float*)d_in[2];
    const float* g1     = (const float*)d_in[3];
    const float* be1    = (const float*)d_in[4];
    const float* w2     = (const float*)d_in[5];
    const float* b2     = (const float*)d_in[6];
    const float* g2     = (const float*)d_in[7];
    const float* be2    = (const float*)d_in[8];
    const float* w3     = (const float*)d_in[9];
    const float* b3     = (const float*)d_in[10];
    const float* gumbel = (const float*)d_in[11];

    proj_kernel<<<NB * NN, NF>>>(nodes, w1, b1);
    dim3 grid(NT, NB);
    edge_kernel<<<grid, 256>>>(g1, be1, w2, b2, g2, be2, w3, b3, gumbel,
                               (float*)d_out);
}

// round 2
// speedup vs baseline: 2.6984x; 2.6984x over previous
#include <cuda_runtime.h>
#include <cstdint>

static constexpr int NB   = 8;     // batch
static constexpr int NN   = 384;   // nodes
static constexpr int NF   = 64;    // features
static constexpr int NT   = 192;   // sink count / shift
static constexpr int NS   = 5;     // gumbel samples
static constexpr int NSRC = 383;   // gumbel source width
static constexpr int NE   = 55200; // edges per batch (sum_{k} (192+k))
static constexpr int CH   = 256;   // edges per block
static constexpr int NCH  = (NE + CH - 1) / CH;  // 216

// Global scratch
__device__ float g_P [NB * NN * NF];   // P[b][n][f]  = nodes@w1[:64] + b1
__device__ float g_Qt[NB * NF * NN];   // Qt[b][f][n] = (nodes@w1[64:])^T
__device__ float g_logits[NB * NT * NN];

// Dynamic smem layout for mlp_kernel
static constexpr int SM_H1T  = 0;                     // NF*CH floats
static constexpr int SM_W2   = SM_H1T + NF * CH;      // NF*NF floats (g1-folded)
static constexpr int SM_G    = SM_W2 + NF * NF;       // NF
static constexpr int SM_C2   = SM_G + NF;             // NF
static constexpr int SM_GW   = SM_C2 + NF;            // NF
static constexpr int SM_RSTD = SM_GW + NF;            // CH
static constexpr int SM_MR   = SM_RSTD + CH;          // CH
static constexpr int SM_OFF  = SM_MR + CH;            // CH (ints)
static constexpr int SM_SCAL = SM_OFF + CH;           // 2
static constexpr int SMEM_FLOATS = SM_SCAL + 2;
static constexpr int SMEM_BYTES  = SMEM_FLOATS * 4;   // ~85.8 KB

__device__ __forceinline__ unsigned smem_u32(const void* p) {
    unsigned a;
    asm("{ .reg .u64 t; cvta.to.shared.u64 t, %1; cvt.u32.u64 %0, t; }"
        : "=r"(a) : "l"(p));
    return a;
}

// ---------------------------------------------------------------------------
// Kernel 1: factored first-layer projection (tiny)
// ---------------------------------------------------------------------------
__global__ void proj_kernel(const float* __restrict__ nodes,
                            const float* __restrict__ w1,
                            const float* __restrict__ b1) {
    int bn = blockIdx.x;           // 0..NB*NN-1
    int j  = threadIdx.x;          // 0..63
    __shared__ float nd[NF];
    nd[j] = nodes[bn * NF + j];
    __syncthreads();
    float accP = b1[j], accQ = 0.f;
#pragma unroll
    for (int f = 0; f < NF; ++f) {
        accP = fmaf(nd[f], w1[f * NF + j], accP);
        accQ = fmaf(nd[f], w1[(NF + f) * NF + j], accQ);
    }
    g_P[bn * NF + j] = accP;
    int b = bn / NN, n = bn % NN;
    g_Qt[(b * NF + j) * NN + n] = accQ;
}

// ---------------------------------------------------------------------------
// Kernel 2: per-edge second layer as register-blocked GEMM -> logits
// Block = 256-edge flat chunk of one batch. 256 threads.
// ---------------------------------------------------------------------------
__global__ __launch_bounds__(256) void mlp_kernel(
    const float* __restrict__ g1,  const float* __restrict__ be1,
    const float* __restrict__ w2,  const float* __restrict__ b2,
    const float* __restrict__ g2,  const float* __restrict__ be2,
    const float* __restrict__ w3,  const float* __restrict__ b3)
{
    extern __shared__ float sm[];
    float* sH1t  = sm + SM_H1T;
    float* sW2   = sm + SM_W2;
    float* sG    = sm + SM_G;
    float* sC2   = sm + SM_C2;
    float* sGw   = sm + SM_GW;
    float* sRstd = sm + SM_RSTD;
    float* sMr   = sm + SM_MR;
    int*   sOff  = (int*)(sm + SM_OFF);
    float* sScal = sm + SM_SCAL;

    const int tid = threadIdx.x;
    const int b   = blockIdx.y;
    const int e0  = blockIdx.x * CH;

    // Fill sW2 with g1-folded weights: sW2[j][o] = g1[j]*w2[j][o]
    for (int i = tid; i < NF * NF; i += 256) sW2[i] = w2[i] * g1[i >> 6];
    if (tid < NF) sGw[tid] = g2[tid] * w3[tid];
    if (tid == 0) {
        float gs = 0.f, cc = b3[0];
        for (int o = 0; o < NF; ++o) { gs += g2[o] * w3[o]; cc = fmaf(be2[o], w3[o], cc); }
        sScal[0] = gs; sScal[1] = cc;
    }

    // ---- Phase A: H1 (relu of factored layer1), LN1 folded to scalars ----
    int e = e0 + tid;
    bool valid = e < NE;
    int ec = valid ? e : NE - 1;
    // row k: largest k with 192k + k(k-1)/2 <= ec
    int k = (int)floorf(-191.5f + sqrtf(36672.25f + 2.0f * (float)ec));
    k = max(0, min(NT - 1, k));
#define ROWOFF(kk) ((kk) * 192 + (((kk) * ((kk) - 1)) >> 1))
    while (k < NT - 1 && ROWOFF(k + 1) <= ec) ++k;
    while (k > 0 && ROWOFF(k) > ec) --k;
    int c = ec - ROWOFF(k);
#undef ROWOFF
    int r = k + NT;
    sOff[tid] = valid ? (k * NN + c) : -1;

    const float* pp = g_P  + ((size_t)b * NN + r) * NF;   // + j
    const float* qp = g_Qt + (size_t)b * NF * NN + c;     // + j*NN
    float s = 0.f, s2 = 0.f;
#pragma unroll 8
    for (int j = 0; j < NF; ++j) {
        float v = pp[j] + qp[j * NN];
        v = fmaxf(v, 0.f);
        sH1t[j * CH + tid] = v;
        s += v;
        s2 = fmaf(v, v, s2);
    }
    {
        const float inv = 1.f / NF;
        float mu   = s * inv;
        float var  = fmaf(-mu, mu, s2 * inv);
        float rstd = rsqrtf(var + 1e-5f);
        sRstd[tid] = rstd;
        sMr[tid]   = mu * rstd;
    }
    __syncthreads();

    // Per-output LN1 correction terms: G_o = sum_j g1_j w2_jo ; C_o = b2_o + sum_j be1_j w2_jo
    if (tid < NF) {
        float G = 0.f;
        for (int j = 0; j < NF; ++j) G += sW2[j * NF + tid];
        sG[tid] = G;
        float C = b2[tid];
        for (int j = 0; j < NF; ++j) C = fmaf(be1[j], w2[j * NF + tid], C);
        sC2[tid] = C;
    }
    __syncthreads();

    // ---- Phase B: GEMM H1t[64 x 256] x W2[64 x 64], 8 edges x 8 outs/thread ----
    const int og = tid & 7;          // output group
    const int eg = tid >> 3;         // edge group (0..31)
    const int ebase = eg * 8;
    const int obase = og * 8;

    unsigned long long acc[32];      // acc[ep*8+o]: edges (2ep,2ep+1) packed, out obase+o
#pragma unroll
    for (int i = 0; i < 32; ++i) acc[i] = 0ULL;

    unsigned xaddr = smem_u32(&sH1t[ebase]);
    const float4* wrow = (const float4*)(sW2 + obase);   // advance by 16 float4 per j

#pragma unroll 8
    for (int j = 0; j < NF; ++j) {
        unsigned long long xd0, xd1, xd2, xd3;
        asm("ld.shared.v2.u64 {%0,%1}, [%2];" : "=l"(xd0), "=l"(xd1) : "r"(xaddr));
        asm("ld.shared.v2.u64 {%0,%1}, [%2];" : "=l"(xd2), "=l"(xd3) : "r"(xaddr + 16));
        float4 wa = wrow[0];
        float4 wb = wrow[1];
        unsigned long long wd[8];
        asm("mov.b64 %0, {%1,%1};" : "=l"(wd[0]) : "f"(wa.x));
        asm("mov.b64 %0, {%1,%1};" : "=l"(wd[1]) : "f"(wa.y));
        asm("mov.b64 %0, {%1,%1};" : "=l"(wd[2]) : "f"(wa.z));
        asm("mov.b64 %0, {%1,%1};" : "=l"(wd[3]) : "f"(wa.w));
        asm("mov.b64 %0, {%1,%1};" : "=l"(wd[4]) : "f"(wb.x));
        asm("mov.b64 %0, {%1,%1};" : "=l"(wd[5]) : "f"(wb.y));
        asm("mov.b64 %0, {%1,%1};" : "=l"(wd[6]) : "f"(wb.z));
        asm("mov.b64 %0, {%1,%1};" : "=l"(wd[7]) : "f"(wb.w));
#pragma unroll
        for (int o = 0; o < 8; ++o) {
            asm("fma.rn.f32x2 %0, %1, %2, %0;" : "+l"(acc[0 * 8 + o]) : "l"(xd0), "l"(wd[o]));
            asm("fma.rn.f32x2 %0, %1, %2, %0;" : "+l"(acc[1 * 8 + o]) : "l"(xd1), "l"(wd[o]));
            asm("fma.rn.f32x2 %0, %1, %2, %0;" : "+l"(acc[2 * 8 + o]) : "l"(xd2), "l"(wd[o]));
            asm("fma.rn.f32x2 %0, %1, %2, %0;" : "+l"(acc[3 * 8 + o]) : "l"(xd3), "l"(wd[o]));
        }
        xaddr += CH * 4;
        wrow  += NF / 4;
    }

    // ---- Epilogue: LN1 correction + relu + LN2/w3 folded sums ----
    float Gr[8], Cr[8], gwv[8];
#pragma unroll
    for (int o = 0; o < 8; ++o) {
        Gr[o]  = sG[obase + o];
        Cr[o]  = sC2[obase + o];
        gwv[o] = sGw[obase + o];
    }
    float S1[8], Sq[8], S3[8];
#pragma unroll
    for (int i = 0; i < 8; ++i) { S1[i] = 0.f; Sq[i] = 0.f; S3[i] = 0.f; }

#pragma unroll
    for (int ep = 0; ep < 4; ++ep) {
        float r0 = sRstd[ebase + 2 * ep],     m0 = sMr[ebase + 2 * ep];
        float r1 = sRstd[ebase + 2 * ep + 1], m1 = sMr[ebase + 2 * ep + 1];
#pragma unroll
        for (int o = 0; o < 8; ++o) {
            float a0, a1;
            asm("mov.b64 {%0,%1}, %2;" : "=f"(a0), "=f"(a1) : "l"(acc[ep * 8 + o]));
            float h0 = fmaf(r0, a0, fmaf(-m0, Gr[o], Cr[o]));
            float h1 = fmaf(r1, a1, fmaf(-m1, Gr[o], Cr[o]));
            h0 = fmaxf(h0, 0.f);
            h1 = fmaxf(h1, 0.f);
            int ei0 = 2 * ep, ei1 = 2 * ep + 1;
            S1[ei0] += h0;  Sq[ei0] = fmaf(h0, h0, Sq[ei0]);  S3[ei0] = fmaf(h0, gwv[o], S3[ei0]);
            S1[ei1] += h1;  Sq[ei1] = fmaf(h1, h1, Sq[ei1]);  S3[ei1] = fmaf(h1, gwv[o], S3[ei1]);
        }
    }

    // Reduce over the 8 output-groups (lane bits 0..2)
#pragma unroll
    for (int d = 1; d < 8; d <<= 1) {
#pragma unroll
        for (int i = 0; i < 8; ++i) {
            S1[i] += __shfl_xor_sync(0xffffffffu, S1[i], d);
            Sq[i] += __shfl_xor_sync(0xffffffffu, Sq[i], d);
            S3[i] += __shfl_xor_sync(0xffffffffu, S3[i], d);
        }
    }

    if (og == 0) {
        float gsum = sScal[0], ccst = sScal[1];
        const float inv = 1.f / NF;
#pragma unroll
        for (int i = 0; i < 8; ++i) {
            float mu2   = S1[i] * inv;
            float var2  = fmaf(-mu2, mu2, Sq[i] * inv);
            float rstd2 = rsqrtf(var2 + 1e-5f);
            float logit = fmaf(rstd2, fmaf(-mu2, gsum, S3[i]), ccst);
            int offv = sOff[ebase + i];
            if (offv >= 0)
                g_logits[(size_t)b * NT * NN + offv] = logit;
        }
    }
}

// ---------------------------------------------------------------------------
// Kernel 3: per-(k,b) gumbel argmax union + output write
// ---------------------------------------------------------------------------
__global__ __launch_bounds__(256) void argmax_kernel(
    const float* __restrict__ gumbel, float* __restrict__ out)
{
    const int k = blockIdx.x;
    const int b = blockIdx.y;
    const int r = k + NT;
    const int nsrc = r;
    const int tid = threadIdx.x;

    __shared__ float sLog[NN];
    __shared__ float sSel[NN];

    for (int c = tid; c < NN; c += 256) sSel[c] = 0.f;
    for (int c = tid; c < nsrc; c += 256)
        sLog[c] = g_logits[((size_t)b * NT + k) * NN + c];
    __syncthreads();

    int wid = tid >> 5, lane = tid & 31;
    if (wid < NS) {
        const float* gu = gumbel + (((size_t)wid * NB + b) * NT + k) * NSRC;
        float best = -__int_as_float(0x7f800000);
        int   bi   = 0;
        for (int c = lane; c < nsrc; c += 32) {
            float v = sLog[c] + gu[c];
            if (v > best) { best = v; bi = c; }
        }
#pragma unroll
        for (int off = 16; off; off >>= 1) {
            float ov = __shfl_down_sync(0xffffffffu, best, off);
            int   oi = __shfl_down_sync(0xffffffffu, bi,   off);
            if (ov > best || (ov == best && oi < bi)) { best = ov; bi = oi; }
        }
        if (lane == 0) sSel[bi] = 1.f;   // union over samples (e>0 binarize)
    }
    __syncthreads();

    float* rowR = out + ((size_t)b * NN + r) * NN;
    float* rowK = out + ((size_t)b * NN + k) * NN;
    for (int c = tid; c < NN; c += 256) {
        rowR[c] = sSel[c];
        rowK[c] = 0.f;
    }
}

// ---------------------------------------------------------------------------
extern "C" void kernel_launch(void* const* d_in, const int* in_sizes, int n_in,
                              void* d_out, int out_size) {
    const float* nodes  = (const float*)d_in[0];
    const float* w1     = (const float*)d_in[1];
    const float* b1     = (const float*)d_in[2];
    const float* g1     = (const float*)d_in[3];
    const float* be1    = (const float*)d_in[4];
    const float* w2     = (const float*)d_in[5];
    const float* b2     = (const float*)d_in[6];
    const float* g2     = (const float*)d_in[7];
    const float* be2    = (const float*)d_in[8];
    const float* w3     = (const float*)d_in[9];
    const float* b3     = (const float*)d_in[10];
    const float* gumbel = (const float*)d_in[11];

    cudaFuncSetAttribute(mlp_kernel,
                         cudaFuncAttributeMaxDynamicSharedMemorySize, SMEM_BYTES);

    proj_kernel<<<NB * NN, NF>>>(nodes, w1, b1);

    dim3 grid2(NCH, NB);
    mlp_kernel<<<grid2, 256, SMEM_BYTES>>>(g1, be1, w2, b2, g2, be2, w3, b3);

    dim3 grid3(NT, NB);
    argmax_kernel<<<grid3, 256>>>(gumbel, (float*)d_out);
}

// round 4
// speedup vs baseline: 3.0658x; 1.1361x over previous
#include <cuda_runtime.h>
#include <cstdint>

static constexpr int NB   = 8;
static constexpr int NN   = 384;
static constexpr int NF   = 64;
static constexpr int NT   = 192;
static constexpr int NS   = 5;
static constexpr int NSRC = 383;
static constexpr int NE   = 55200;          // edges per batch
static constexpr int ETOT = NB * NE;        // 441600
static constexpr int CH   = 128;            // edges per block
static constexpr int NBLK = ETOT / CH;      // 3450 exact

static constexpr int VSTR = 136;            // sV row stride (8 mod 32 -> conflict-free frags)

// ---------------- global scratch ----------------
__device__ float g_P [NB * NN * NF];        // P[b][n][f]
__device__ float g_Qt[NB * NF * NN];        // Qt[b][f][n]
__device__ float g_logits[NB * NT * NN];
__device__ float g_Whi[4096];               // W2 A-fragments hi: [s][om][lane][4]
__device__ float g_Wlo[4096];
__device__ float g_Go[64], g_Co[64], g_Gw[64];
__device__ float g_scal[2];                 // gsum, ccst

__device__ __forceinline__ float tf32r(float x) {
    uint32_t u;
    asm("cvt.rna.tf32.f32 %0, %1;" : "=r"(u) : "f"(x));
    return __uint_as_float(u);
}

#define MMA_TF32(dd, av, b0, b1) \
    asm volatile("mma.sync.aligned.m16n8k8.row.col.f32.tf32.tf32.f32 " \
        "{%0,%1,%2,%3}, {%4,%5,%6,%7}, {%8,%9}, {%0,%1,%2,%3};" \
        : "+f"((dd)[0]), "+f"((dd)[1]), "+f"((dd)[2]), "+f"((dd)[3]) \
        : "r"(__float_as_uint((av).x)), "r"(__float_as_uint((av).y)), \
          "r"(__float_as_uint((av).z)), "r"(__float_as_uint((av).w)), \
          "r"(b0), "r"(b1))

#define ROWOFF(kk) ((kk) * 192 + (((kk) * ((kk) - 1)) >> 1))

// ---------------------------------------------------------------------------
// Kernel 0: constant prep — W2 tf32 fragments + folded LN vectors
// A[m=o][k=j] = g1[j]*w2[j][o]; fragment slot t = ((s*4+om)*32+lane)
// ---------------------------------------------------------------------------
__global__ void setup_kernel(const float* __restrict__ w2,
                             const float* __restrict__ g1,
                             const float* __restrict__ be1,
                             const float* __restrict__ b2,
                             const float* __restrict__ g2,
                             const float* __restrict__ be2,
                             const float* __restrict__ w3,
                             const float* __restrict__ b3) {
    int t = threadIdx.x;                  // 0..1023
    int s = t >> 7, om = (t >> 5) & 3, lane = t & 31;
    int g = lane >> 2, tig = lane & 3;
    int o1 = om * 16 + g, o2 = o1 + 8;
    int j1 = 8 * s + tig, j2 = j1 + 4;
    float a[4];
    a[0] = g1[j1] * w2[j1 * 64 + o1];
    a[1] = g1[j1] * w2[j1 * 64 + o2];
    a[2] = g1[j2] * w2[j2 * 64 + o1];
    a[3] = g1[j2] * w2[j2 * 64 + o2];
#pragma unroll
    for (int rr = 0; rr < 4; ++rr) {
        float hi = tf32r(a[rr]);
        float lo = tf32r(a[rr] - hi);
        g_Whi[t * 4 + rr] = hi;
        g_Wlo[t * 4 + rr] = lo;
    }
    if (t < 64) {
        float G = 0.f, C = b2[t];
        for (int j = 0; j < 64; ++j) {
            G += g1[j] * w2[j * 64 + t];
            C = fmaf(be1[j], w2[j * 64 + t], C);
        }
        g_Go[t] = G;
        g_Co[t] = C;
        g_Gw[t] = g2[t] * w3[t];
    }
    if (t == 0) {
        float gs = 0.f, cc = b3[0];
        for (int o = 0; o < 64; ++o) { gs += g2[o] * w3[o]; cc = fmaf(be2[o], w3[o], cc); }
        g_scal[0] = gs;
        g_scal[1] = cc;
    }
}

// ---------------------------------------------------------------------------
// Kernel 1: factored first-layer projection (w1 staged in smem, 16 nodes/blk)
// ---------------------------------------------------------------------------
__global__ __launch_bounds__(256) void proj_kernel(const float* __restrict__ nodes,
                                                   const float* __restrict__ w1,
                                                   const float* __restrict__ b1) {
    __shared__ float sW[128 * 64];
    __shared__ float sNd[16 * 64];
    const int tid = threadIdx.x;
    for (int i = tid; i < 128 * 64; i += 256) sW[i] = w1[i];
    const int n0 = blockIdx.x * 16;
    for (int i = tid; i < 16 * 64; i += 256) sNd[i] = nodes[n0 * 64 + i];
    __syncthreads();

    const int nl = tid >> 4;
    const int og = tid & 15;
    const bool isP = og < 8;
    const int colb = (og & 7) * 8;

    float acc[8];
#pragma unroll
    for (int i = 0; i < 8; ++i) acc[i] = 0.f;
    const float* nd = &sNd[nl * 64];
    const float* wp = sW + (isP ? 0 : 64 * 64) + colb;
#pragma unroll 16
    for (int f = 0; f < 64; ++f) {
        float x = nd[f];
        const float4* w4 = (const float4*)(wp + f * 64);
        float4 a = w4[0], bq = w4[1];
        acc[0] = fmaf(x, a.x, acc[0]);  acc[1] = fmaf(x, a.y, acc[1]);
        acc[2] = fmaf(x, a.z, acc[2]);  acc[3] = fmaf(x, a.w, acc[3]);
        acc[4] = fmaf(x, bq.x, acc[4]); acc[5] = fmaf(x, bq.y, acc[5]);
        acc[6] = fmaf(x, bq.z, acc[6]); acc[7] = fmaf(x, bq.w, acc[7]);
    }
    const int gn = n0 + nl;
    if (isP) {
#pragma unroll
        for (int i = 0; i < 8; ++i)
            g_P[gn * 64 + colb + i] = acc[i] + b1[colb + i];
    } else {
        const int bb = gn / NN, n = gn % NN;
#pragma unroll
        for (int i = 0; i < 8; ++i)
            g_Qt[((size_t)bb * 64 + colb + i) * NN + n] = acc[i];
    }
}

// ---------------------------------------------------------------------------
// Kernel 2: edge MLP — phase A (relu+split into smem) + phase B (mma.sync tf32)
// block = 128 flat edges, 256 threads (8 warps: 2 o-halves x 4 edge-quarters)
// ---------------------------------------------------------------------------
// smem float offsets
static constexpr int SVH = 0;                 // 64*136
static constexpr int SVL = SVH + 64 * VSTR;   // 64*136
static constexpr int SRS = SVL + 64 * VSTR;   // 128 rstd
static constexpr int SMU = SRS + 128;         // 128 mu*rstd
static constexpr int SP1 = SMU + 128;         // 128 partial s
static constexpr int SP2 = SP1 + 128;         // 128 partial s2
static constexpr int SR1 = SP2 + 128;         // 128 red S1
static constexpr int SRQ = SR1 + 128;         // 128 red Sq
static constexpr int SR3 = SRQ + 128;         // 128 red S3
static constexpr int SGO = SR3 + 128;         // 64
static constexpr int SCO = SGO + 64;          // 64
static constexpr int SGW = SCO + 64;          // 64
static constexpr int SOF = SGW + 64;          // 128 (int)
static constexpr int SSC = SOF + 128;         // 2
static constexpr int SMEM_FLOATS = SSC + 2;
static constexpr int SMEM_BYTES = SMEM_FLOATS * 4;

__global__ __launch_bounds__(256, 2) void mlp_kernel() {
    extern __shared__ float sm[];
    const int tid  = threadIdx.x;
    const int lane = tid & 31;
    const int wid  = tid >> 5;

    // constants to smem
    if (tid < 64) {
        sm[SGO + tid] = g_Go[tid];
        sm[SCO + tid] = g_Co[tid];
        sm[SGW + tid] = g_Gw[tid];
    }
    if (tid == 0) { sm[SSC] = g_scal[0]; sm[SSC + 1] = g_scal[1]; }

    // ---- phase A: 2 threads per edge (k halves of 32) ----
    const int el = tid & 127;
    const int kh = tid >> 7;
    const int k0 = kh * 32;
    const int E  = blockIdx.x * CH + el;
    const int b  = E / NE;
    const int eb = E - b * NE;
    int k = (int)floorf(-191.5f + sqrtf(36672.25f + 2.0f * (float)eb));
    k = max(0, min(NT - 1, k));
    while (k < NT - 1 && ROWOFF(k + 1) <= eb) ++k;
    while (k > 0 && ROWOFF(k) > eb) --k;
    const int c = eb - ROWOFF(k);
    const int r = k + NT;
    if (kh == 0) ((int*)sm)[SOF + el] = (b * NT + k) * NN + c;

    {
        const float* pp = g_P + ((size_t)(b * NN + r)) * 64 + k0;
        const float* qp = g_Qt + ((size_t)(b * 64 + k0)) * NN + c;
        float pv[32];
        const float4* p4 = (const float4*)pp;
#pragma unroll
        for (int i = 0; i < 8; ++i) {
            float4 t4 = p4[i];
            pv[4 * i] = t4.x; pv[4 * i + 1] = t4.y; pv[4 * i + 2] = t4.z; pv[4 * i + 3] = t4.w;
        }
        float s1 = 0.f, s2 = 0.f;
#pragma unroll
        for (int j = 0; j < 32; ++j) {
            float v = fmaxf(pv[j] + qp[j * NN], 0.f);
            s1 += v;
            s2 = fmaf(v, v, s2);
            float hi = tf32r(v);
            float lo = tf32r(v - hi);
            sm[SVH + (k0 + j) * VSTR + el] = hi;
            sm[SVL + (k0 + j) * VSTR + el] = lo;
        }
        if (kh) { sm[SP1 + el] = s1; sm[SP2 + el] = s2; }
        __syncthreads();
        if (!kh) {
            s1 += sm[SP1 + el];
            s2 += sm[SP2 + el];
            const float inv = 1.f / 64.f;
            float mu   = s1 * inv;
            float rstd = rsqrtf(fmaf(-mu, mu, s2 * inv) + 1e-5f);
            sm[SRS + el] = rstd;
            sm[SMU + el] = mu * rstd;
        }
    }
    __syncthreads();

    // ---- phase B: mma.sync tf32, 3xTF32 ----
    const int g     = lane >> 2;
    const int tig   = lane & 3;
    const int ohalf = wid >> 2;
    const int eb0   = (wid & 3) * 32;

    float d[2][4][4];
#pragma unroll
    for (int mt = 0; mt < 2; ++mt)
#pragma unroll
        for (int nt = 0; nt < 4; ++nt)
#pragma unroll
            for (int q = 0; q < 4; ++q) d[mt][nt][q] = 0.f;

    const float4* WH = (const float4*)g_Whi;
    const float4* WL = (const float4*)g_Wlo;

#pragma unroll
    for (int s = 0; s < 8; ++s) {
        float4 ah0 = WH[(s * 4 + ohalf * 2 + 0) * 32 + lane];
        float4 ah1 = WH[(s * 4 + ohalf * 2 + 1) * 32 + lane];
        float4 al0 = WL[(s * 4 + ohalf * 2 + 0) * 32 + lane];
        float4 al1 = WL[(s * 4 + ohalf * 2 + 1) * 32 + lane];
        const int row0 = (8 * s + tig) * VSTR;
        const int row1 = row0 + 4 * VSTR;
        uint32_t bh0[4], bh1[4], bl0[4], bl1[4];
#pragma unroll
        for (int nt = 0; nt < 4; ++nt) {
            int col = eb0 + nt * 8 + g;
            bh0[nt] = __float_as_uint(sm[SVH + row0 + col]);
            bh1[nt] = __float_as_uint(sm[SVH + row1 + col]);
            bl0[nt] = __float_as_uint(sm[SVL + row0 + col]);
            bl1[nt] = __float_as_uint(sm[SVL + row1 + col]);
        }
#pragma unroll
        for (int nt = 0; nt < 4; ++nt) {
            MMA_TF32(d[0][nt], ah0, bh0[nt], bh1[nt]);
            MMA_TF32(d[1][nt], ah1, bh0[nt], bh1[nt]);
            MMA_TF32(d[0][nt], ah0, bl0[nt], bl1[nt]);
            MMA_TF32(d[1][nt], ah1, bl0[nt], bl1[nt]);
            MMA_TF32(d[0][nt], al0, bh0[nt], bh1[nt]);
            MMA_TF32(d[1][nt], al1, bh0[nt], bh1[nt]);
        }
    }

    // ---- epilogue: LN1 correction + relu + LN2/w3 folded sums ----
    const int ob = ohalf * 32;
    const float Go0 = sm[SGO + ob + g],      Co0 = sm[SCO + ob + g],      Gw0 = sm[SGW + ob + g];
    const float Go1 = sm[SGO + ob + g + 8],  Co1 = sm[SCO + ob + g + 8],  Gw1 = sm[SGW + ob + g + 8];
    const float Go2 = sm[SGO + ob + g + 16], Co2 = sm[SCO + ob + g + 16], Gw2 = sm[SGW + ob + g + 16];
    const float Go3 = sm[SGO + ob + g + 24], Co3 = sm[SCO + ob + g + 24], Gw3 = sm[SGW + ob + g + 24];

    float S1[4][2], SQ[4][2], S3[4][2];
#pragma unroll
    for (int nt = 0; nt < 4; ++nt)
#pragma unroll
        for (int h = 0; h < 2; ++h) {
            int ecol = eb0 + nt * 8 + 2 * tig + h;
            float rstd = sm[SRS + ecol];
            float mur  = sm[SMU + ecol];
            float h0 = fmaxf(fmaf(d[0][nt][h],     rstd, fmaf(-mur, Go0, Co0)), 0.f);
            float h1 = fmaxf(fmaf(d[0][nt][2 + h], rstd, fmaf(-mur, Go1, Co1)), 0.f);
            float h2 = fmaxf(fmaf(d[1][nt][h],     rstd, fmaf(-mur, Go2, Co2)), 0.f);
            float h3 = fmaxf(fmaf(d[1][nt][2 + h], rstd, fmaf(-mur, Go3, Co3)), 0.f);
            S1[nt][h] = h0 + h1 + h2 + h3;
            SQ[nt][h] = fmaf(h0, h0, fmaf(h1, h1, fmaf(h2, h2, h3 * h3)));
            S3[nt][h] = fmaf(h0, Gw0, fmaf(h1, Gw1, fmaf(h2, Gw2, h3 * Gw3)));
        }

#pragma unroll
    for (int m = 4; m <= 16; m <<= 1) {
#pragma unroll
        for (int nt = 0; nt < 4; ++nt)
#pragma unroll
            for (int h = 0; h < 2; ++h) {
                S1[nt][h] += __shfl_xor_sync(0xffffffffu, S1[nt][h], m);
                SQ[nt][h] += __shfl_xor_sync(0xffffffffu, SQ[nt][h], m);
                S3[nt][h] += __shfl_xor_sync(0xffffffffu, S3[nt][h], m);
            }
    }

    if (ohalf == 0 && g == 0) {
#pragma unroll
        for (int nt = 0; nt < 4; ++nt)
#pragma unroll
            for (int h = 0; h < 2; ++h) {
                int ecol = eb0 + nt * 8 + 2 * tig + h;
                sm[SR1 + ecol] = S1[nt][h];
                sm[SRQ + ecol] = SQ[nt][h];
                sm[SR3 + ecol] = S3[nt][h];
            }
    }
    __syncthreads();
    if (ohalf == 1 && g == 0) {
        const float gsum = sm[SSC], ccst = sm[SSC + 1];
        const float inv = 1.f / 64.f;
#pragma unroll
        for (int nt = 0; nt < 4; ++nt)
#pragma unroll
            for (int h = 0; h < 2; ++h) {
                int ecol = eb0 + nt * 8 + 2 * tig + h;
                float t1 = S1[nt][h] + sm[SR1 + ecol];
                float tq = SQ[nt][h] + sm[SRQ + ecol];
                float t3 = S3[nt][h] + sm[SR3 + ecol];
                float mu2   = t1 * inv;
                float rstd2 = rsqrtf(fmaf(-mu2, mu2, tq * inv) + 1e-5f);
                float logit = fmaf(rstd2, fmaf(-mu2, gsum, t3), ccst);
                g_logits[((int*)sm)[SOF + ecol]] = logit;
            }
    }
}

// ---------------------------------------------------------------------------
// Kernel 3: per-(k,b) gumbel argmax union + output write
// ---------------------------------------------------------------------------
__global__ __launch_bounds__(256) void argmax_kernel(
    const float* __restrict__ gumbel, float* __restrict__ out)
{
    const int k = blockIdx.x;
    const int b = blockIdx.y;
    const int r = k + NT;
    const int nsrc = r;
    const int tid = threadIdx.x;

    __shared__ float sLog[NN];
    __shared__ float sSel[NN];

    for (int c = tid; c < NN; c += 256) sSel[c] = 0.f;
    for (int c = tid; c < nsrc; c += 256)
        sLog[c] = g_logits[((size_t)b * NT + k) * NN + c];
    __syncthreads();

    int wid = tid >> 5, lane = tid & 31;
    if (wid < NS) {
        const float* gu = gumbel + (((size_t)wid * NB + b) * NT + k) * NSRC;
        float best = -__int_as_float(0x7f800000);
        int   bi   = 0;
        for (int c = lane; c < nsrc; c += 32) {
            float v = sLog[c] + gu[c];
            if (v > best) { best = v; bi = c; }
        }
#pragma unroll
        for (int off = 16; off; off >>= 1) {
            float ov = __shfl_down_sync(0xffffffffu, best, off);
            int   oi = __shfl_down_sync(0xffffffffu, bi,   off);
            if (ov > best || (ov == best && oi < bi)) { best = ov; bi = oi; }
        }
        if (lane == 0) sSel[bi] = 1.f;
    }
    __syncthreads();

    float* rowR = out + ((size_t)b * NN + r) * NN;
    float* rowK = out + ((size_t)b * NN + k) * NN;
    for (int c = tid; c < NN; c += 256) {
        rowR[c] = sSel[c];
        rowK[c] = 0.f;
    }
}

// ---------------------------------------------------------------------------
extern "C" void kernel_launch(void* const* d_in, const int* in_sizes, int n_in,
                              void* d_out, int out_size) {
    const float* nodes  = (const float*)d_in[0];
    const float* w1     = (const float*)d_in[1];
    const float* b1     = (const float*)d_in[2];
    const float* g1     = (const float*)d_in[3];
    const float* be1    = (const float*)d_in[4];
    const float* w2     = (const float*)d_in[5];
    const float* b2     = (const float*)d_in[6];
    const float* g2     = (const float*)d_in[7];
    const float* be2    = (const float*)d_in[8];
    const float* w3     = (const float*)d_in[9];
    const float* b3     = (const float*)d_in[10];
    const float* gumbel = (const float*)d_in[11];

    cudaFuncSetAttribute(mlp_kernel,
                         cudaFuncAttributeMaxDynamicSharedMemorySize, SMEM_BYTES);

    setup_kernel<<<1, 1024>>>(w2, g1, be1, b2, g2, be2, w3, b3);
    proj_kernel<<<NB * NN / 16, 256>>>(nodes, w1, b1);
    mlp_kernel<<<NBLK, 256, SMEM_BYTES>>>();
    dim3 grid3(NT, NB);
    argmax_kernel<<<grid3, 256>>>(gumbel, (float*)d_out);
}

// round 6
// speedup vs baseline: 3.3307x; 1.0864x over previous
#include <cuda_runtime.h>
#include <cstdint>

static constexpr int NB   = 8;
static constexpr int NN   = 384;
static constexpr int NF   = 64;
static constexpr int NT   = 192;
static constexpr int NS   = 5;
static constexpr int NSRC = 383;
static constexpr int NE   = 55200;          // edges per batch
static constexpr int ETOT = NB * NE;        // 441600
static constexpr int CH   = 128;            // edges per block
static constexpr int NBLK = ETOT / CH;      // 3450 exact

static constexpr int VSTR = 136;            // sV row stride (8 mod 32 -> conflict-free frags)

// ---------------- global scratch ----------------
__device__ float g_P [NB * NN * NF];        // P[b][n][f]
__device__ float g_Qt[NB * NF * NN];        // Qt[b][f][n]
__device__ float g_logits[NB * NT * NN];
__device__ float g_Whi[4096];               // W2 A-fragments hi: [s][om][lane][4]
__device__ float g_Wlo[4096];
__device__ float g_Go[64], g_Co[64], g_Gw[64];
__device__ float g_scal[2];                 // gsum, ccst

__device__ __forceinline__ float tf32r(float x) {
    uint32_t u;
    asm("cvt.rna.tf32.f32 %0, %1;" : "=r"(u) : "f"(x));
    return __uint_as_float(u);
}

#define MMA_TF32(dd, av, b0, b1) \
    asm volatile("mma.sync.aligned.m16n8k8.row.col.f32.tf32.tf32.f32 " \
        "{%0,%1,%2,%3}, {%4,%5,%6,%7}, {%8,%9}, {%0,%1,%2,%3};" \
        : "+f"((dd)[0]), "+f"((dd)[1]), "+f"((dd)[2]), "+f"((dd)[3]) \
        : "r"(__float_as_uint((av).x)), "r"(__float_as_uint((av).y)), \
          "r"(__float_as_uint((av).z)), "r"(__float_as_uint((av).w)), \
          "r"(b0), "r"(b1))

#define ROWOFF(kk) ((kk) * 192 + (((kk) * ((kk) - 1)) >> 1))

// ---------------------------------------------------------------------------
// Kernel 0: constant prep — W2 tf32 fragments + folded LN vectors
// ---------------------------------------------------------------------------
__global__ void setup_kernel(const float* __restrict__ w2,
                             const float* __restrict__ g1,
                             const float* __restrict__ be1,
                             const float* __restrict__ b2,
                             const float* __restrict__ g2,
                             const float* __restrict__ be2,
                             const float* __restrict__ w3,
                             const float* __restrict__ b3) {
    int t = threadIdx.x;                  // 0..1023
    int s = t >> 7, om = (t >> 5) & 3, lane = t & 31;
    int g = lane >> 2, tig = lane & 3;
    int o1 = om * 16 + g, o2 = o1 + 8;
    int j1 = 8 * s + tig, j2 = j1 + 4;
    float a[4];
    a[0] = g1[j1] * w2[j1 * 64 + o1];
    a[1] = g1[j1] * w2[j1 * 64 + o2];
    a[2] = g1[j2] * w2[j2 * 64 + o1];
    a[3] = g1[j2] * w2[j2 * 64 + o2];
#pragma unroll
    for (int rr = 0; rr < 4; ++rr) {
        float hi = tf32r(a[rr]);
        float lo = tf32r(a[rr] - hi);
        g_Whi[t * 4 + rr] = hi;
        g_Wlo[t * 4 + rr] = lo;
    }
    if (t < 64) {
        float G = 0.f, C = b2[t];
        for (int j = 0; j < 64; ++j) {
            G += g1[j] * w2[j * 64 + t];
            C = fmaf(be1[j], w2[j * 64 + t], C);
        }
        g_Go[t] = G;
        g_Co[t] = C;
        g_Gw[t] = g2[t] * w3[t];
    }
    if (t == 0) {
        float gs = 0.f, cc = b3[0];
        for (int o = 0; o < 64; ++o) { gs += g2[o] * w3[o]; cc = fmaf(be2[o], w3[o], cc); }
        g_scal[0] = gs;
        g_scal[1] = cc;
    }
}

// ---------------------------------------------------------------------------
// Kernel 1: factored first-layer projection
// ---------------------------------------------------------------------------
__global__ __launch_bounds__(256) void proj_kernel(const float* __restrict__ nodes,
                                                   const float* __restrict__ w1,
                                                   const float* __restrict__ b1) {
    __shared__ float sW[128 * 64];
    __shared__ float sNd[16 * 64];
    const int tid = threadIdx.x;
    for (int i = tid; i < 128 * 64; i += 256) sW[i] = w1[i];
    const int n0 = blockIdx.x * 16;
    for (int i = tid; i < 16 * 64; i += 256) sNd[i] = nodes[n0 * 64 + i];
    __syncthreads();

    const int nl = tid >> 4;
    const int og = tid & 15;
    const bool isP = og < 8;
    const int colb = (og & 7) * 8;

    float acc[8];
#pragma unroll
    for (int i = 0; i < 8; ++i) acc[i] = 0.f;
    const float* nd = &sNd[nl * 64];
    const float* wp = sW + (isP ? 0 : 64 * 64) + colb;
#pragma unroll 16
    for (int f = 0; f < 64; ++f) {
        float x = nd[f];
        const float4* w4 = (const float4*)(wp + f * 64);
        float4 a = w4[0], bq = w4[1];
        acc[0] = fmaf(x, a.x, acc[0]);  acc[1] = fmaf(x, a.y, acc[1]);
        acc[2] = fmaf(x, a.z, acc[2]);  acc[3] = fmaf(x, a.w, acc[3]);
        acc[4] = fmaf(x, bq.x, acc[4]); acc[5] = fmaf(x, bq.y, acc[5]);
        acc[6] = fmaf(x, bq.z, acc[6]); acc[7] = fmaf(x, bq.w, acc[7]);
    }
    const int gn = n0 + nl;
    if (isP) {
#pragma unroll
        for (int i = 0; i < 8; ++i)
            g_P[gn * 64 + colb + i] = acc[i] + b1[colb + i];
    } else {
        const int bb = gn / NN, n = gn % NN;
#pragma unroll
        for (int i = 0; i < 8; ++i)
            g_Qt[((size_t)bb * 64 + colb + i) * NN + n] = acc[i];
    }
}

// ---------------------------------------------------------------------------
// Kernel 2: edge MLP — phase A (relu+split into smem) + phase B (mma.sync tf32)
// ---------------------------------------------------------------------------
static constexpr int SVH = 0;                 // 64*136
static constexpr int SVL = SVH + 64 * VSTR;   // 64*136
static constexpr int SRS = SVL + 64 * VSTR;   // 128 rstd
static constexpr int SMU = SRS + 128;         // 128 mu*rstd
static constexpr int SP1 = SMU + 128;         // 128 partial s
static constexpr int SP2 = SP1 + 128;         // 128 partial s2
static constexpr int SR1 = SP2 + 128;         // 128 red S1
static constexpr int SRQ = SR1 + 128;         // 128 red Sq
static constexpr int SR3 = SRQ + 128;         // 128 red S3
static constexpr int SGO = SR3 + 128;         // 64
static constexpr int SCO = SGO + 64;          // 64
static constexpr int SGW = SCO + 64;          // 64
static constexpr int SOF = SGW + 64;          // 128 (int)
static constexpr int SSC = SOF + 128;         // 2
static constexpr int SMEM_FLOATS = SSC + 2;
static constexpr int SMEM_BYTES = SMEM_FLOATS * 4;

__global__ __launch_bounds__(256, 3) void mlp_kernel() {
    extern __shared__ float sm[];
    const int tid  = threadIdx.x;
    const int lane = tid & 31;
    const int wid  = tid >> 5;

    if (tid < 64) {
        sm[SGO + tid] = g_Go[tid];
        sm[SCO + tid] = g_Co[tid];
        sm[SGW + tid] = g_Gw[tid];
    }
    if (tid == 0) { sm[SSC] = g_scal[0]; sm[SSC + 1] = g_scal[1]; }

    // ---- phase A: 2 threads per edge (k halves of 32) ----
    const int el = tid & 127;
    const int kh = tid >> 7;
    const int k0 = kh * 32;
    const int E  = blockIdx.x * CH + el;
    const int b  = E / NE;
    const int eb = E - b * NE;
    int k = (int)floorf(-191.5f + sqrtf(36672.25f + 2.0f * (float)eb));
    k = max(0, min(NT - 1, k));
    while (k < NT - 1 && ROWOFF(k + 1) <= eb) ++k;
    while (k > 0 && ROWOFF(k) > eb) --k;
    const int c = eb - ROWOFF(k);
    const int r = k + NT;
    if (kh == 0) ((int*)sm)[SOF + el] = (b * NT + k) * NN + c;

    {
        const float* pp = g_P + ((size_t)(b * NN + r)) * 64 + k0;
        const float* qp = g_Qt + ((size_t)(b * 64 + k0)) * NN + c;
        float pv[32];
        const float4* p4 = (const float4*)pp;
#pragma unroll
        for (int i = 0; i < 8; ++i) {
            float4 t4 = p4[i];
            pv[4 * i] = t4.x; pv[4 * i + 1] = t4.y; pv[4 * i + 2] = t4.z; pv[4 * i + 3] = t4.w;
        }
        float s1 = 0.f, s2 = 0.f;
#pragma unroll
        for (int j = 0; j < 32; ++j) {
            float v = fmaxf(pv[j] + qp[j * NN], 0.f);
            s1 += v;
            s2 = fmaf(v, v, s2);
            float hi = tf32r(v);
            float lo = tf32r(v - hi);
            sm[SVH + (k0 + j) * VSTR + el] = hi;
            sm[SVL + (k0 + j) * VSTR + el] = lo;
        }
        if (kh) { sm[SP1 + el] = s1; sm[SP2 + el] = s2; }
        __syncthreads();
        if (!kh) {
            s1 += sm[SP1 + el];
            s2 += sm[SP2 + el];
            const float inv = 1.f / 64.f;
            float mu   = s1 * inv;
            float rstd = rsqrtf(fmaf(-mu, mu, s2 * inv) + 1e-5f);
            sm[SRS + el] = rstd;
            sm[SMU + el] = mu * rstd;
        }
    }
    __syncthreads();

    // ---- phase B: mma.sync tf32, 3xTF32 (register-lean pass ordering) ----
    const int g     = lane >> 2;
    const int tig   = lane & 3;
    const int ohalf = wid >> 2;
    const int eb0   = (wid & 3) * 32;

    float d[2][4][4];
#pragma unroll
    for (int mt = 0; mt < 2; ++mt)
#pragma unroll
        for (int nt = 0; nt < 4; ++nt)
#pragma unroll
            for (int q = 0; q < 4; ++q) d[mt][nt][q] = 0.f;

    const float4* WH = (const float4*)g_Whi;
    const float4* WL = (const float4*)g_Wlo;

#pragma unroll
    for (int s = 0; s < 8; ++s) {
        const int row0 = (8 * s + tig) * VSTR;
        const int row1 = row0 + 4 * VSTR;
        // B-hi fragments
        uint32_t b0[4], b1[4];
#pragma unroll
        for (int nt = 0; nt < 4; ++nt) {
            int col = eb0 + nt * 8 + g;
            b0[nt] = __float_as_uint(sm[SVH + row0 + col]);
            b1[nt] = __float_as_uint(sm[SVH + row1 + col]);
        }
        float4 ah0 = WH[(s * 4 + ohalf * 2 + 0) * 32 + lane];
        float4 ah1 = WH[(s * 4 + ohalf * 2 + 1) * 32 + lane];
#pragma unroll
        for (int nt = 0; nt < 4; ++nt) {
            MMA_TF32(d[0][nt], ah0, b0[nt], b1[nt]);
            MMA_TF32(d[1][nt], ah1, b0[nt], b1[nt]);
        }
        float4 al0 = WL[(s * 4 + ohalf * 2 + 0) * 32 + lane];
        float4 al1 = WL[(s * 4 + ohalf * 2 + 1) * 32 + lane];
#pragma unroll
        for (int nt = 0; nt < 4; ++nt) {
            MMA_TF32(d[0][nt], al0, b0[nt], b1[nt]);
            MMA_TF32(d[1][nt], al1, b0[nt], b1[nt]);
        }
        // B-lo fragments (reuse b regs)
#pragma unroll
        for (int nt = 0; nt < 4; ++nt) {
            int col = eb0 + nt * 8 + g;
            b0[nt] = __float_as_uint(sm[SVL + row0 + col]);
            b1[nt] = __float_as_uint(sm[SVL + row1 + col]);
        }
#pragma unroll
        for (int nt = 0; nt < 4; ++nt) {
            MMA_TF32(d[0][nt], ah0, b0[nt], b1[nt]);
            MMA_TF32(d[1][nt], ah1, b0[nt], b1[nt]);
        }
    }

    // ---- epilogue: LN1 correction + relu + LN2/w3 folded sums ----
    const int ob = ohalf * 32;
    const float Go0 = sm[SGO + ob + g],      Co0 = sm[SCO + ob + g],      Gw0 = sm[SGW + ob + g];
    const float Go1 = sm[SGO + ob + g + 8],  Co1 = sm[SCO + ob + g + 8],  Gw1 = sm[SGW + ob + g + 8];
    const float Go2 = sm[SGO + ob + g + 16], Co2 = sm[SCO + ob + g + 16], Gw2 = sm[SGW + ob + g + 16];
    const float Go3 = sm[SGO + ob + g + 24], Co3 = sm[SCO + ob + g + 24], Gw3 = sm[SGW + ob + g + 24];

    float S1[4][2], SQ[4][2], S3[4][2];
#pragma unroll
    for (int nt = 0; nt < 4; ++nt)
#pragma unroll
        for (int h = 0; h < 2; ++h) {
            int ecol = eb0 + nt * 8 + 2 * tig + h;
            float rstd = sm[SRS + ecol];
            float mur  = sm[SMU + ecol];
            float h0 = fmaxf(fmaf(d[0][nt][h],     rstd, fmaf(-mur, Go0, Co0)), 0.f);
            float h1 = fmaxf(fmaf(d[0][nt][2 + h], rstd, fmaf(-mur, Go1, Co1)), 0.f);
            float h2 = fmaxf(fmaf(d[1][nt][h],     rstd, fmaf(-mur, Go2, Co2)), 0.f);
            float h3 = fmaxf(fmaf(d[1][nt][2 + h], rstd, fmaf(-mur, Go3, Co3)), 0.f);
            S1[nt][h] = h0 + h1 + h2 + h3;
            SQ[nt][h] = fmaf(h0, h0, fmaf(h1, h1, fmaf(h2, h2, h3 * h3)));
            S3[nt][h] = fmaf(h0, Gw0, fmaf(h1, Gw1, fmaf(h2, Gw2, h3 * Gw3)));
        }

#pragma unroll
    for (int m = 4; m <= 16; m <<= 1) {
#pragma unroll
        for (int nt = 0; nt < 4; ++nt)
#pragma unroll
            for (int h = 0; h < 2; ++h) {
                S1[nt][h] += __shfl_xor_sync(0xffffffffu, S1[nt][h], m);
                SQ[nt][h] += __shfl_xor_sync(0xffffffffu, SQ[nt][h], m);
                S3[nt][h] += __shfl_xor_sync(0xffffffffu, S3[nt][h], m);
            }
    }

    if (ohalf == 0 && g == 0) {
#pragma unroll
        for (int nt = 0; nt < 4; ++nt)
#pragma unroll
            for (int h = 0; h < 2; ++h) {
                int ecol = eb0 + nt * 8 + 2 * tig + h;
                sm[SR1 + ecol] = S1[nt][h];
                sm[SRQ + ecol] = SQ[nt][h];
                sm[SR3 + ecol] = S3[nt][h];
            }
    }
    __syncthreads();
    if (ohalf == 1 && g == 0) {
        const float gsum = sm[SSC], ccst = sm[SSC + 1];
        const float inv = 1.f / 64.f;
#pragma unroll
        for (int nt = 0; nt < 4; ++nt)
#pragma unroll
            for (int h = 0; h < 2; ++h) {
                int ecol = eb0 + nt * 8 + 2 * tig + h;
                float t1 = S1[nt][h] + sm[SR1 + ecol];
                float tq = SQ[nt][h] + sm[SRQ + ecol];
                float t3 = S3[nt][h] + sm[SR3 + ecol];
                float mu2   = t1 * inv;
                float rstd2 = rsqrtf(fmaf(-mu2, mu2, tq * inv) + 1e-5f);
                float logit = fmaf(rstd2, fmaf(-mu2, gsum, t3), ccst);
                g_logits[((int*)sm)[SOF + ecol]] = logit;
            }
    }
}

// ---------------------------------------------------------------------------
// Kernel 3: per-(k,b) gumbel argmax union + output write
// 160 threads (5 active warps), 4 independent scan chains per lane
// ---------------------------------------------------------------------------
__global__ __launch_bounds__(160) void argmax_kernel(
    const float* __restrict__ gumbel, float* __restrict__ out)
{
    const int k = blockIdx.x;
    const int b = blockIdx.y;
    const int r = k + NT;
    const int nsrc = r;
    const int tid = threadIdx.x;

    __shared__ float sLog[NN];
    __shared__ float sSel[NN];

    for (int c = tid; c < NN; c += 160) sSel[c] = 0.f;
    for (int c = tid; c < nsrc; c += 160)
        sLog[c] = g_logits[((size_t)b * NT + k) * NN + c];
    __syncthreads();

    const int wid = tid >> 5, lane = tid & 31;
    {
        const float* gu = gumbel + (((size_t)wid * NB + b) * NT + k) * NSRC;
        const float NEGINF = -__int_as_float(0x7f800000);
        float best[4];
        int   bi[4];
#pragma unroll
        for (int q = 0; q < 4; ++q) { best[q] = NEGINF; bi[q] = 0x7fffffff; }
        for (int c0 = lane; c0 < nsrc; c0 += 128) {
#pragma unroll
            for (int q = 0; q < 4; ++q) {
                int cc = c0 + 32 * q;
                if (cc < nsrc) {
                    float v = sLog[cc] + gu[cc];
                    if (v > best[q]) { best[q] = v; bi[q] = cc; }  // ascending -> first idx
                }
            }
        }
        // merge 4 chains (value desc, index asc tiebreak)
        float bv = best[0]; int bx = bi[0];
#pragma unroll
        for (int q = 1; q < 4; ++q)
            if (best[q] > bv || (best[q] == bv && bi[q] < bx)) { bv = best[q]; bx = bi[q]; }
#pragma unroll
        for (int off = 16; off; off >>= 1) {
            float ov = __shfl_down_sync(0xffffffffu, bv, off);
            int   oi = __shfl_down_sync(0xffffffffu, bx, off);
            if (ov > bv || (ov == bv && oi < bx)) { bv = ov; bx = oi; }
        }
        if (lane == 0) sSel[bx] = 1.f;
    }
    __syncthreads();

    float* rowR = out + ((size_t)b * NN + r) * NN;
    float* rowK = out + ((size_t)b * NN + k) * NN;
    for (int c = tid; c < NN; c += 160) {
        rowR[c] = sSel[c];
        rowK[c] = 0.f;
    }
}

// ---------------------------------------------------------------------------
extern "C" void kernel_launch(void* const* d_in, const int* in_sizes, int n_in,
                              void* d_out, int out_size) {
    const float* nodes  = (const float*)d_in[0];
    const float* w1     = (const float*)d_in[1];
    const float* b1     = (const float*)d_in[2];
    const float* g1     = (const float*)d_in[3];
    const float* be1    = (const float*)d_in[4];
    const float* w2     = (const float*)d_in[5];
    const float* b2     = (const float*)d_in[6];
    const float* g2     = (const float*)d_in[7];
    const float* be2    = (const float*)d_in[8];
    const float* w3     = (const float*)d_in[9];
    const float* b3     = (const float*)d_in[10];
    const float* gumbel = (const float*)d_in[11];

    cudaFuncSetAttribute(mlp_kernel,
                         cudaFuncAttributeMaxDynamicSharedMemorySize, SMEM_BYTES);

    setup_kernel<<<1, 1024>>>(w2, g1, be1, b2, g2, be2, w3, b3);
    proj_kernel<<<NB * NN / 16, 256>>>(nodes, w1, b1);
    mlp_kernel<<<NBLK, 256, SMEM_BYTES>>>();
    dim3 grid3(NT, NB);
    argmax_kernel<<<grid3, 160>>>(gumbel, (float*)d_out);
}

// round 7
// speedup vs baseline: 3.7962x; 1.1398x over previous
#include <cuda_runtime.h>
#include <cstdint>

static constexpr int NB   = 8;
static constexpr int NN   = 384;
static constexpr int NF   = 64;
static constexpr int NT   = 192;
static constexpr int NS   = 5;
static constexpr int NSRC = 383;
static constexpr int NE   = 55200;
static constexpr int ETOT = NB * NE;        // 441600
static constexpr int CH   = 128;
static constexpr int NBLK = ETOT / CH;      // 3450

static constexpr int VSTR = 136;            // conflict-free B-fragment stride

// ---------------- global scratch ----------------
__device__ float g_P [NB * NN * NF];
__device__ float g_Qt[NB * NF * NN];
__device__ float g_logits[NB * NT * NN];    // single-pass tf32 approx
__device__ float g_Whi[4096];               // W2 A-fragments (tf32 hi)
__device__ float g_W2f[4096];               // g1-folded W2, [j][o] (exact refine)
__device__ float g_Go[64], g_Co[64], g_Gw[64];
__device__ float g_scal[2];

__device__ __forceinline__ float tf32r(float x) {
    uint32_t u;
    asm("cvt.rna.tf32.f32 %0, %1;" : "=r"(u) : "f"(x));
    return __uint_as_float(u);
}

#define MMA_TF32(dd, av, b0, b1) \
    asm volatile("mma.sync.aligned.m16n8k8.row.col.f32.tf32.tf32.f32 " \
        "{%0,%1,%2,%3}, {%4,%5,%6,%7}, {%8,%9}, {%0,%1,%2,%3};" \
        : "+f"((dd)[0]), "+f"((dd)[1]), "+f"((dd)[2]), "+f"((dd)[3]) \
        : "r"(__float_as_uint((av).x)), "r"(__float_as_uint((av).y)), \
          "r"(__float_as_uint((av).z)), "r"(__float_as_uint((av).w)), \
          "r"(b0), "r"(b1))

#define ROWOFF(kk) ((kk) * 192 + (((kk) * ((kk) - 1)) >> 1))

// ---------------------------------------------------------------------------
// Kernel 0: constants — tf32 A-fragments, exact folded weights, LN folds
// ---------------------------------------------------------------------------
__global__ void setup_kernel(const float* __restrict__ w2,
                             const float* __restrict__ g1,
                             const float* __restrict__ be1,
                             const float* __restrict__ b2,
                             const float* __restrict__ g2,
                             const float* __restrict__ be2,
                             const float* __restrict__ w3,
                             const float* __restrict__ b3) {
    int t = threadIdx.x;                  // 0..1023
    int s = t >> 7, om = (t >> 5) & 3, lane = t & 31;
    int g = lane >> 2, tig = lane & 3;
    int o1 = om * 16 + g, o2 = o1 + 8;
    int j1 = 8 * s + tig, j2 = j1 + 4;
    g_Whi[t * 4 + 0] = tf32r(g1[j1] * w2[j1 * 64 + o1]);
    g_Whi[t * 4 + 1] = tf32r(g1[j1] * w2[j1 * 64 + o2]);
    g_Whi[t * 4 + 2] = tf32r(g1[j2] * w2[j2 * 64 + o1]);
    g_Whi[t * 4 + 3] = tf32r(g1[j2] * w2[j2 * 64 + o2]);
#pragma unroll
    for (int q = 0; q < 4; ++q) {
        int i = t * 4 + q;                // [j][o]
        g_W2f[i] = g1[i >> 6] * w2[i];
    }
    if (t < 64) {
        float G = 0.f, C = b2[t];
        for (int j = 0; j < 64; ++j) {
            G += g1[j] * w2[j * 64 + t];
            C = fmaf(be1[j], w2[j * 64 + t], C);
        }
        g_Go[t] = G;
        g_Co[t] = C;
        g_Gw[t] = g2[t] * w3[t];
    }
    if (t == 0) {
        float gs = 0.f, cc = b3[0];
        for (int o = 0; o < 64; ++o) { gs += g2[o] * w3[o]; cc = fmaf(be2[o], w3[o], cc); }
        g_scal[0] = gs;
        g_scal[1] = cc;
    }
}

// ---------------------------------------------------------------------------
// Kernel 1: factored first-layer projection
// ---------------------------------------------------------------------------
__global__ __launch_bounds__(256) void proj_kernel(const float* __restrict__ nodes,
                                                   const float* __restrict__ w1,
                                                   const float* __restrict__ b1) {
    __shared__ float sW[128 * 64];
    __shared__ float sNd[16 * 64];
    const int tid = threadIdx.x;
    for (int i = tid; i < 128 * 64; i += 256) sW[i] = w1[i];
    const int n0 = blockIdx.x * 16;
    for (int i = tid; i < 16 * 64; i += 256) sNd[i] = nodes[n0 * 64 + i];
    __syncthreads();

    const int nl = tid >> 4;
    const int og = tid & 15;
    const bool isP = og < 8;
    const int colb = (og & 7) * 8;

    float acc[8];
#pragma unroll
    for (int i = 0; i < 8; ++i) acc[i] = 0.f;
    const float* nd = &sNd[nl * 64];
    const float* wp = sW + (isP ? 0 : 64 * 64) + colb;
#pragma unroll 16
    for (int f = 0; f < 64; ++f) {
        float x = nd[f];
        const float4* w4 = (const float4*)(wp + f * 64);
        float4 a = w4[0], bq = w4[1];
        acc[0] = fmaf(x, a.x, acc[0]);  acc[1] = fmaf(x, a.y, acc[1]);
        acc[2] = fmaf(x, a.z, acc[2]);  acc[3] = fmaf(x, a.w, acc[3]);
        acc[4] = fmaf(x, bq.x, acc[4]); acc[5] = fmaf(x, bq.y, acc[5]);
        acc[6] = fmaf(x, bq.z, acc[6]); acc[7] = fmaf(x, bq.w, acc[7]);
    }
    const int gn = n0 + nl;
    if (isP) {
#pragma unroll
        for (int i = 0; i < 8; ++i)
            g_P[gn * 64 + colb + i] = acc[i] + b1[colb + i];
    } else {
        const int bb = gn / NN, n = gn % NN;
#pragma unroll
        for (int i = 0; i < 8; ++i)
            g_Qt[((size_t)bb * 64 + colb + i) * NN + n] = acc[i];
    }
}

// ---------------------------------------------------------------------------
// Kernel 2: edge MLP — single-pass TF32 mma.sync
// ---------------------------------------------------------------------------
static constexpr int SVH = 0;                 // 64*VSTR
static constexpr int SRS = SVH + 64 * VSTR;   // 128 rstd
static constexpr int SMU = SRS + 128;
static constexpr int SP1 = SMU + 128;
static constexpr int SP2 = SP1 + 128;
static constexpr int SR1 = SP2 + 128;
static constexpr int SRQ = SR1 + 128;
static constexpr int SR3 = SRQ + 128;
static constexpr int SGO = SR3 + 128;         // 64
static constexpr int SCO = SGO + 64;
static constexpr int SGW = SCO + 64;
static constexpr int SOF = SGW + 64;          // 128 int
static constexpr int SSC = SOF + 128;
static constexpr int SMEM_FLOATS = SSC + 2;
static constexpr int SMEM_BYTES = SMEM_FLOATS * 4;

__global__ __launch_bounds__(256, 3) void mlp_kernel() {
    extern __shared__ float sm[];
    const int tid  = threadIdx.x;
    const int lane = tid & 31;
    const int wid  = tid >> 5;

    if (tid < 64) {
        sm[SGO + tid] = g_Go[tid];
        sm[SCO + tid] = g_Co[tid];
        sm[SGW + tid] = g_Gw[tid];
    }
    if (tid == 0) { sm[SSC] = g_scal[0]; sm[SSC + 1] = g_scal[1]; }

    // ---- phase A: 2 threads per edge ----
    const int el = tid & 127;
    const int kh = tid >> 7;
    const int k0 = kh * 32;
    const int E  = blockIdx.x * CH + el;
    const int b  = E / NE;
    const int eb = E - b * NE;
    int k = (int)floorf(-191.5f + sqrtf(36672.25f + 2.0f * (float)eb));
    k = max(0, min(NT - 1, k));
    while (k < NT - 1 && ROWOFF(k + 1) <= eb) ++k;
    while (k > 0 && ROWOFF(k) > eb) --k;
    const int c = eb - ROWOFF(k);
    const int r = k + NT;
    if (kh == 0) ((int*)sm)[SOF + el] = (b * NT + k) * NN + c;

    {
        const float* pp = g_P + ((size_t)(b * NN + r)) * 64 + k0;
        const float* qp = g_Qt + ((size_t)(b * 64 + k0)) * NN + c;
        float pv[32];
        const float4* p4 = (const float4*)pp;
#pragma unroll
        for (int i = 0; i < 8; ++i) {
            float4 t4 = p4[i];
            pv[4 * i] = t4.x; pv[4 * i + 1] = t4.y; pv[4 * i + 2] = t4.z; pv[4 * i + 3] = t4.w;
        }
        float s1 = 0.f, s2 = 0.f;
#pragma unroll
        for (int j = 0; j < 32; ++j) {
            float v = fmaxf(pv[j] + qp[j * NN], 0.f);
            s1 += v;
            s2 = fmaf(v, v, s2);
            sm[SVH + (k0 + j) * VSTR + el] = tf32r(v);
        }
        if (kh) { sm[SP1 + el] = s1; sm[SP2 + el] = s2; }
        __syncthreads();
        if (!kh) {
            s1 += sm[SP1 + el];
            s2 += sm[SP2 + el];
            const float inv = 1.f / 64.f;
            float mu   = s1 * inv;
            float rstd = rsqrtf(fmaf(-mu, mu, s2 * inv) + 1e-5f);
            sm[SRS + el] = rstd;
            sm[SMU + el] = mu * rstd;
        }
    }
    __syncthreads();

    // ---- phase B: single-pass mma ----
    const int g     = lane >> 2;
    const int tig   = lane & 3;
    const int ohalf = wid >> 2;
    const int eb0   = (wid & 3) * 32;

    float d[2][4][4];
#pragma unroll
    for (int mt = 0; mt < 2; ++mt)
#pragma unroll
        for (int nt = 0; nt < 4; ++nt)
#pragma unroll
            for (int q = 0; q < 4; ++q) d[mt][nt][q] = 0.f;

    const float4* WH = (const float4*)g_Whi;

#pragma unroll
    for (int s = 0; s < 8; ++s) {
        const int row0 = (8 * s + tig) * VSTR;
        const int row1 = row0 + 4 * VSTR;
        uint32_t b0[4], b1[4];
#pragma unroll
        for (int nt = 0; nt < 4; ++nt) {
            int col = eb0 + nt * 8 + g;
            b0[nt] = __float_as_uint(sm[SVH + row0 + col]);
            b1[nt] = __float_as_uint(sm[SVH + row1 + col]);
        }
        float4 ah0 = WH[(s * 4 + ohalf * 2 + 0) * 32 + lane];
        float4 ah1 = WH[(s * 4 + ohalf * 2 + 1) * 32 + lane];
#pragma unroll
        for (int nt = 0; nt < 4; ++nt) {
            MMA_TF32(d[0][nt], ah0, b0[nt], b1[nt]);
            MMA_TF32(d[1][nt], ah1, b0[nt], b1[nt]);
        }
    }

    // ---- epilogue ----
    const int ob = ohalf * 32;
    const float Go0 = sm[SGO + ob + g],      Co0 = sm[SCO + ob + g],      Gw0 = sm[SGW + ob + g];
    const float Go1 = sm[SGO + ob + g + 8],  Co1 = sm[SCO + ob + g + 8],  Gw1 = sm[SGW + ob + g + 8];
    const float Go2 = sm[SGO + ob + g + 16], Co2 = sm[SCO + ob + g + 16], Gw2 = sm[SGW + ob + g + 16];
    const float Go3 = sm[SGO + ob + g + 24], Co3 = sm[SCO + ob + g + 24], Gw3 = sm[SGW + ob + g + 24];

    float S1[4][2], SQ[4][2], S3[4][2];
#pragma unroll
    for (int nt = 0; nt < 4; ++nt)
#pragma unroll
        for (int h = 0; h < 2; ++h) {
            int ecol = eb0 + nt * 8 + 2 * tig + h;
            float rstd = sm[SRS + ecol];
            float mur  = sm[SMU + ecol];
            float h0 = fmaxf(fmaf(d[0][nt][h],     rstd, fmaf(-mur, Go0, Co0)), 0.f);
            float h1 = fmaxf(fmaf(d[0][nt][2 + h], rstd, fmaf(-mur, Go1, Co1)), 0.f);
            float h2 = fmaxf(fmaf(d[1][nt][h],     rstd, fmaf(-mur, Go2, Co2)), 0.f);
            float h3 = fmaxf(fmaf(d[1][nt][2 + h], rstd, fmaf(-mur, Go3, Co3)), 0.f);
            S1[nt][h] = h0 + h1 + h2 + h3;
            SQ[nt][h] = fmaf(h0, h0, fmaf(h1, h1, fmaf(h2, h2, h3 * h3)));
            S3[nt][h] = fmaf(h0, Gw0, fmaf(h1, Gw1, fmaf(h2, Gw2, h3 * Gw3)));
        }

#pragma unroll
    for (int m = 4; m <= 16; m <<= 1) {
#pragma unroll
        for (int nt = 0; nt < 4; ++nt)
#pragma unroll
            for (int h = 0; h < 2; ++h) {
                S1[nt][h] += __shfl_xor_sync(0xffffffffu, S1[nt][h], m);
                SQ[nt][h] += __shfl_xor_sync(0xffffffffu, SQ[nt][h], m);
                S3[nt][h] += __shfl_xor_sync(0xffffffffu, S3[nt][h], m);
            }
    }

    if (ohalf == 0 && g == 0) {
#pragma unroll
        for (int nt = 0; nt < 4; ++nt)
#pragma unroll
            for (int h = 0; h < 2; ++h) {
                int ecol = eb0 + nt * 8 + 2 * tig + h;
                sm[SR1 + ecol] = S1[nt][h];
                sm[SRQ + ecol] = SQ[nt][h];
                sm[SR3 + ecol] = S3[nt][h];
            }
    }
    __syncthreads();
    if (ohalf == 1 && g == 0) {
        const float gsum = sm[SSC], ccst = sm[SSC + 1];
        const float inv = 1.f / 64.f;
#pragma unroll
        for (int nt = 0; nt < 4; ++nt)
#pragma unroll
            for (int h = 0; h < 2; ++h) {
                int ecol = eb0 + nt * 8 + 2 * tig + h;
                float t1 = S1[nt][h] + sm[SR1 + ecol];
                float tq = SQ[nt][h] + sm[SRQ + ecol];
                float t3 = S3[nt][h] + sm[SR3 + ecol];
                float mu2   = t1 * inv;
                float rstd2 = rsqrtf(fmaf(-mu2, mu2, tq * inv) + 1e-5f);
                float logit = fmaf(rstd2, fmaf(-mu2, gsum, t3), ccst);
                g_logits[((int*)sm)[SOF + ecol]] = logit;
            }
    }
}

// ---------------------------------------------------------------------------
// Kernel 3: argmax with exact-fp32 rescue of near-ties (window 0.06)
// ---------------------------------------------------------------------------
static constexpr float CAND_WIN = 0.06f;

__global__ __launch_bounds__(256) void argmax_kernel(
    const float* __restrict__ gumbel, float* __restrict__ out)
{
    __shared__ float sW2f[4096];     // exact folded W2 [j][o]
    __shared__ float sLog[NN];
    __shared__ float sSel[NN];
    __shared__ float sZ[NS * NN];
    __shared__ float sP[64];
    __shared__ float sVc[NS * 64];
    __shared__ int   sCand[NS * 32];

    const int k = blockIdx.x;
    const int b = blockIdx.y;
    const int r = k + NT;
    const int nsrc = r;
    const int tid = threadIdx.x;
    const int wid = tid >> 5, lane = tid & 31;

    for (int i = tid; i < 4096; i += 256) sW2f[i] = g_W2f[i];
    if (tid < 64) sP[tid] = g_P[((size_t)b * NN + r) * 64 + tid];
    for (int c = tid; c < NN; c += 256) sSel[c] = 0.f;
    for (int c = tid; c < nsrc; c += 256)
        sLog[c] = g_logits[((size_t)b * NT + k) * NN + c];
    __syncthreads();

    if (wid < NS) {
        const float* gu = gumbel + (((size_t)wid * NB + b) * NT + k) * NSRC;
        const float NEGINF = -__int_as_float(0x7f800000);

        // pass 1: z = approx logit + gumbel -> smem; track max (4 ILP chains)
        float best[4];
#pragma unroll
        for (int q = 0; q < 4; ++q) best[q] = NEGINF;
        for (int c0 = lane; c0 < nsrc; c0 += 128) {
#pragma unroll
            for (int q = 0; q < 4; ++q) {
                int cc = c0 + 32 * q;
                if (cc < nsrc) {
                    float z = sLog[cc] + gu[cc];
                    sZ[wid * NN + cc] = z;
                    best[q] = fmaxf(best[q], z);
                }
            }
        }
        float m = fmaxf(fmaxf(best[0], best[1]), fmaxf(best[2], best[3]));
#pragma unroll
        for (int off = 16; off; off >>= 1)
            m = fmaxf(m, __shfl_xor_sync(0xffffffffu, m, off));
        const float thr = m - CAND_WIN;
        __syncwarp();

        // pass 2: collect candidates in ascending index order
        int cnt = 0;
        for (int c0 = 0; c0 < nsrc; c0 += 32) {
            int cc = c0 + lane;
            float z = (cc < nsrc) ? sZ[wid * NN + cc] : NEGINF;
            unsigned msk = __ballot_sync(0xffffffffu, z >= thr);
            if (lane == 0) {
                while (msk) {
                    int bit = __ffs(msk) - 1;
                    if (cnt < 32) sCand[wid * 32 + cnt] = c0 + bit;
                    ++cnt;
                    msk &= msk - 1;
                }
            }
        }
        cnt = __shfl_sync(0xffffffffu, cnt, 0);
        if (cnt > 32) cnt = 32;
        __syncwarp();

        int sel = sCand[wid * 32];
        if (cnt > 1) {
            // exact fp32 rescoring of candidates (same algebra as always-exact path)
            float bz = NEGINF;
            for (int q = 0; q < cnt; ++q) {
                int cc = sCand[wid * 32 + q];
                float q0 = g_Qt[((size_t)b * 64 + lane) * NN + cc];
                float q1 = g_Qt[((size_t)b * 64 + lane + 32) * NN + cc];
                float v0 = fmaxf(sP[lane] + q0, 0.f);
                float v1 = fmaxf(sP[lane + 32] + q1, 0.f);
                sVc[wid * 64 + lane] = v0;
                sVc[wid * 64 + lane + 32] = v1;
                float s1 = v0 + v1;
                float s2 = fmaf(v0, v0, v1 * v1);
#pragma unroll
                for (int off = 16; off; off >>= 1) {
                    s1 += __shfl_xor_sync(0xffffffffu, s1, off);
                    s2 += __shfl_xor_sync(0xffffffffu, s2, off);
                }
                const float inv = 1.f / 64.f;
                float mu   = s1 * inv;
                float rstd = rsqrtf(fmaf(-mu, mu, s2 * inv) + 1e-5f);
                __syncwarp();
                float a0 = 0.f, a1 = 0.f;
#pragma unroll 8
                for (int j = 0; j < 64; ++j) {
                    float vv = sVc[wid * 64 + j];
                    a0 = fmaf(vv, sW2f[j * 64 + lane], a0);
                    a1 = fmaf(vv, sW2f[j * 64 + lane + 32], a1);
                }
                float mur = mu * rstd;
                float h0 = fmaxf(fmaf(rstd, a0, fmaf(-mur, g_Go[lane], g_Co[lane])), 0.f);
                float h1 = fmaxf(fmaf(rstd, a1, fmaf(-mur, g_Go[lane + 32], g_Co[lane + 32])), 0.f);
                float S1 = h0 + h1;
                float Sq = fmaf(h0, h0, h1 * h1);
                float S3 = fmaf(h0, g_Gw[lane], h1 * g_Gw[lane + 32]);
#pragma unroll
                for (int off = 16; off; off >>= 1) {
                    S1 += __shfl_xor_sync(0xffffffffu, S1, off);
                    Sq += __shfl_xor_sync(0xffffffffu, Sq, off);
                    S3 += __shfl_xor_sync(0xffffffffu, S3, off);
                }
                float mu2   = S1 * inv;
                float rstd2 = rsqrtf(fmaf(-mu2, mu2, Sq * inv) + 1e-5f);
                float lg    = fmaf(rstd2, fmaf(-mu2, g_scal[0], S3), g_scal[1]);
                float z     = lg + __ldg(&gu[cc]);
                if (z > bz) { bz = z; sel = cc; }   // ascending list -> first index wins ties
                __syncwarp();
            }
        }
        if (lane == 0) sSel[sel] = 1.f;
    }
    __syncthreads();

    float* rowR = out + ((size_t)b * NN + r) * NN;
    float* rowK = out + ((size_t)b * NN + k) * NN;
    for (int c = tid; c < NN; c += 256) {
        rowR[c] = sSel[c];
        rowK[c] = 0.f;
    }
}

// ---------------------------------------------------------------------------
extern "C" void kernel_launch(void* const* d_in, const int* in_sizes, int n_in,
                              void* d_out, int out_size) {
    const float* nodes  = (const float*)d_in[0];
    const float* w1     = (const float*)d_in[1];
    const float* b1     = (const float*)d_in[2];
    const float* g1     = (const float*)d_in[3];
    const float* be1    = (const float*)d_in[4];
    const float* w2     = (const float*)d_in[5];
    const float* b2     = (const float*)d_in[6];
    const float* g2     = (const float*)d_in[7];
    const float* be2    = (const float*)d_in[8];
    const float* w3     = (const float*)d_in[9];
    const float* b3     = (const float*)d_in[10];
    const float* gumbel = (const float*)d_in[11];

    cudaFuncSetAttribute(mlp_kernel,
                         cudaFuncAttributeMaxDynamicSharedMemorySize, SMEM_BYTES);

    setup_kernel<<<1, 1024>>>(w2, g1, be1, b2, g2, be2, w3, b3);
    proj_kernel<<<NB * NN / 16, 256>>>(nodes, w1, b1);
    mlp_kernel<<<NBLK, 256, SMEM_BYTES>>>();
    dim3 grid3(NT, NB);
    argmax_kernel<<<grid3, 256>>>(gumbel, (float*)d_out);
}